// round 6
// baseline (speedup 1.0000x reference)
#include <cuda_runtime.h>
#include <cuda_bf16.h>

// ---------------------------------------------------------------------------
// Fused LSTM(2)->bridge->GRU(2, autoregressive)->MLP predictor.
// B=2048, H=128, S=64. 512 blocks x 4 rows, 256 threads, 4 CTAs/SM.
// Tile: 2 gates x 4 rows per thread (fma.rn.f32x2 packed over k).
// LSTM layer-wavefront; GRU n-gates fused; MLP head folded into gate phases.
// ---------------------------------------------------------------------------

#define NROWS 4
#define NTHREADS 256
#define NBLOCKS 512   // 2048 / 4
#define SEQ 64
#define H 128

// ----- scratch layout (floats), identical to validated layout -----
#define OFF_W0    0
#define OFF_W1    67584
#define OFF_GRZ0  198656
#define OFF_GRZ1  264192
#define OFF_WIN0  329728
#define OFF_WHN0  346112
#define OFF_WIN1  362496
#define OFF_WHN1  378880
#define OFF_BR    395264
#define OFF_FC1   411648
#define OFF_B0    419840
#define OFF_B1    420352
#define OFF_BRZ0  420864
#define OFF_BRZ1  421120
#define OFF_BIN0  421376
#define OFF_BHN0  421504
#define OFF_BIN1  421632
#define OFF_BHN1  421760
#define OFF_BB    421888
#define OFF_FC1B  422016
#define SCRATCH_TOTAL 422080

__device__ __align__(16) float g_scratch[SCRATCH_TOTAL];

// dynamic smem layout (floats)
#define SM_ST   0                     // st[4][384]
#define SM_C0   (NROWS*384)           // c0s[4][128]
#define SM_C1   (SM_C0 + NROWS*128)   // c1s[4][128]
#define SM_GB0  (SM_C1 + NROWS*128)   // gb0[4][512]
#define SM_GB1  (SM_GB0 + NROWS*512)  // gb1[4][512]
#define SM_XS   (SM_GB1 + NROWS*512)  // xs[4][256]
#define SM_GBH  (SM_XS + NROWS*256)   // gbH[4][64]
#define SM_TOTAL (SM_GBH + NROWS*64)  // 7936 floats = 31744 bytes
#define SMEM_BYTES (SM_TOTAL * 4)

// ---------------------------------------------------------------------------
// Prep kernel (unchanged, validated)
// ---------------------------------------------------------------------------
__global__ void prep_kernel(
    const float* __restrict__ wih0, const float* __restrict__ whh0,
    const float* __restrict__ bih0, const float* __restrict__ bhh0,
    const float* __restrict__ wih1, const float* __restrict__ whh1,
    const float* __restrict__ bih1, const float* __restrict__ bhh1,
    const float* __restrict__ gwih0, const float* __restrict__ gwhh0,
    const float* __restrict__ gbih0, const float* __restrict__ gbhh0,
    const float* __restrict__ gwih1, const float* __restrict__ gwhh1,
    const float* __restrict__ gbih1, const float* __restrict__ gbhh1,
    const float* __restrict__ brw,  const float* __restrict__ brb,
    const float* __restrict__ fc1w, const float* __restrict__ fc1b)
{
    int idx = blockIdx.x * blockDim.x + threadIdx.x;
    if (idx >= SCRATCH_TOTAL) return;
    float v = 0.0f;

    if (idx < OFF_W1) {
        int i = idx - OFF_W0;
        int kk = i & 3; int j = i >> 2; int g = j & 511; int k4 = j >> 9;
        int k = 4*k4 + kk;
        v = (k < 4) ? wih0[g*4 + k] : whh0[g*128 + (k - 4)];
    } else if (idx < OFF_GRZ0) {
        int i = idx - OFF_W1;
        int kk = i & 3; int j = i >> 2; int g = j & 511; int k4 = j >> 9;
        int k = 4*k4 + kk;
        v = (k < 128) ? wih1[g*128 + k] : whh1[g*128 + (k - 128)];
    } else if (idx < OFF_GRZ1) {
        int i = idx - OFF_GRZ0;
        int kk = i & 3; int j = i >> 2; int g = j & 255; int k4 = j >> 8;
        int k = 4*k4 + kk;
        v = (k < 128) ? gwih0[g*128 + k] : gwhh0[g*128 + (k - 128)];
    } else if (idx < OFF_WIN0) {
        int i = idx - OFF_GRZ1;
        int kk = i & 3; int j = i >> 2; int g = j & 255; int k4 = j >> 8;
        int k = 4*k4 + kk;
        v = (k < 128) ? gwih1[g*128 + k] : gwhh1[g*128 + (k - 128)];
    } else if (idx < OFF_WHN0) {
        int i = idx - OFF_WIN0;
        int kk = i & 3; int j = i >> 2; int g = j & 127; int k4 = j >> 7;
        v = gwih0[(256 + g)*128 + 4*k4 + kk];
    } else if (idx < OFF_WIN1) {
        int i = idx - OFF_WHN0;
        int kk = i & 3; int j = i >> 2; int g = j & 127; int k4 = j >> 7;
        v = gwhh0[(256 + g)*128 + 4*k4 + kk];
    } else if (idx < OFF_WHN1) {
        int i = idx - OFF_WIN1;
        int kk = i & 3; int j = i >> 2; int g = j & 127; int k4 = j >> 7;
        v = gwih1[(256 + g)*128 + 4*k4 + kk];
    } else if (idx < OFF_BR) {
        int i = idx - OFF_WHN1;
        int kk = i & 3; int j = i >> 2; int g = j & 127; int k4 = j >> 7;
        v = gwhh1[(256 + g)*128 + 4*k4 + kk];
    } else if (idx < OFF_FC1) {
        int i = idx - OFF_BR;
        int kk = i & 3; int j = i >> 2; int g = j & 127; int k4 = j >> 7;
        v = brw[g*128 + 4*k4 + kk];
    } else if (idx < OFF_B0) {
        int i = idx - OFF_FC1;
        int kk = i & 3; int j = i >> 2; int g = j & 63; int k4 = j >> 6;
        v = fc1w[g*128 + 4*k4 + kk];
    } else if (idx < OFF_B1)   { int i = idx - OFF_B0;   v = bih0[i] + bhh0[i]; }
    else if (idx < OFF_BRZ0)   { int i = idx - OFF_B1;   v = bih1[i] + bhh1[i]; }
    else if (idx < OFF_BRZ1)   { int i = idx - OFF_BRZ0; v = gbih0[i] + gbhh0[i]; }
    else if (idx < OFF_BIN0)   { int i = idx - OFF_BRZ1; v = gbih1[i] + gbhh1[i]; }
    else if (idx < OFF_BHN0)   { int i = idx - OFF_BIN0; v = gbih0[256 + i]; }
    else if (idx < OFF_BIN1)   { int i = idx - OFF_BHN0; v = gbhh0[256 + i]; }
    else if (idx < OFF_BHN1)   { int i = idx - OFF_BIN1; v = gbih1[256 + i]; }
    else if (idx < OFF_BB)     { int i = idx - OFF_BHN1; v = gbhh1[256 + i]; }
    else if (idx < OFF_FC1B)   { int i = idx - OFF_BB;   v = brb[i]; }
    else                       { int i = idx - OFF_FC1B; v = fc1b[i]; }

    g_scratch[idx] = v;
}

// ---------------------------------------------------------------------------
// Activations (fast-math)
// ---------------------------------------------------------------------------
__device__ __forceinline__ float sigf(float x) {
    x = fminf(fmaxf(x, -30.f), 30.f);
    return __fdividef(1.f, 1.f + __expf(-x));
}
__device__ __forceinline__ float tanhfast(float x) {
    x = fminf(fmaxf(x, -15.f), 15.f);
    float e = __expf(2.f * x);
    return 1.f - __fdividef(2.f, e + 1.f);
}

// ---------------------------------------------------------------------------
// Packed f32x2 FMA
// ---------------------------------------------------------------------------
__device__ __forceinline__ void ffma2(unsigned long long& d,
                                      unsigned long long a,
                                      unsigned long long b) {
    asm("fma.rn.f32x2 %0, %1, %2, %0;" : "+l"(d) : "l"(a), "l"(b));
}
__device__ __forceinline__ float red2(unsigned long long a) {
    float lo = __uint_as_float((unsigned)(a & 0xffffffffull));
    float hi = __uint_as_float((unsigned)(a >> 32));
    return lo + hi;
}

// ---------------------------------------------------------------------------
// Tiled dot: NG gates (stride GW/NG) x 4 rows, f32x2 over k.
// ---------------------------------------------------------------------------
template<int NG, int GW, int K4>
__device__ __forceinline__ void dotG(const float* __restrict__ wbase, int g0,
                                     const float* __restrict__ stp,
                                     unsigned long long acc[NG][4])
{
    const ulonglong2* wq = reinterpret_cast<const ulonglong2*>(wbase);
    #pragma unroll 4
    for (int k4 = 0; k4 < K4; ++k4) {
        ulonglong2 w[NG];
        #pragma unroll
        for (int i = 0; i < NG; ++i)
            w[i] = __ldg(&wq[k4 * GW + g0 + i * (GW / NG)]);
        #pragma unroll
        for (int j = 0; j < 4; ++j) {
            ulonglong2 s = *reinterpret_cast<const ulonglong2*>(stp + j * 384 + 4 * k4);
            #pragma unroll
            for (int i = 0; i < NG; ++i) {
                ffma2(acc[i][j], w[i].x, s.x);
                ffma2(acc[i][j], w[i].y, s.y);
            }
        }
    }
}

// scalar single-row dot (bridge)
template<int GW, int K4>
__device__ __forceinline__ float dot1(const float* __restrict__ wbase, int g,
                                      const float* __restrict__ srow, float acc)
{
    const float4* w4 = reinterpret_cast<const float4*>(wbase);
    const float4* s4 = reinterpret_cast<const float4*>(srow);
    #pragma unroll 4
    for (int k4 = 0; k4 < K4; ++k4) {
        float4 w = __ldg(&w4[k4 * GW + g]);
        float4 s = s4[k4];
        acc = fmaf(w.x, s.x, acc);
        acc = fmaf(w.y, s.y, acc);
        acc = fmaf(w.z, s.z, acc);
        acc = fmaf(w.w, s.w, acc);
    }
    return acc;
}

// ---------------------------------------------------------------------------
// Main fused kernel: 256 threads, 4 rows, 4 CTAs/SM (single wave, 512 CTAs)
// ---------------------------------------------------------------------------
__global__ void __launch_bounds__(NTHREADS, 4)
fused_kernel(const float* __restrict__ x, const int* __restrict__ plen_p,
             const float* __restrict__ fc2w, const float* __restrict__ fc2b,
             float* __restrict__ out)
{
    extern __shared__ float sm[];
    float (*st)[384]  = (float (*)[384])(sm + SM_ST);
    float (*c0s)[128] = (float (*)[128])(sm + SM_C0);
    float (*c1s)[128] = (float (*)[128])(sm + SM_C1);
    float (*gb0)[512] = (float (*)[512])(sm + SM_GB0);
    float (*gb1)[512] = (float (*)[512])(sm + SM_GB1);
    float (*xs)[256]  = (float (*)[256])(sm + SM_XS);
    float (*gbH)[64]  = (float (*)[64])(sm + SM_GBH);
    __shared__ float fc2ws[128];
    __shared__ float fc2bs[2];

    const int tid = threadIdx.x;
    const int rbase = blockIdx.x * NROWS;
    const float* S = g_scratch;
    const int plen = plen_p[0];

    // init: zero state, preload x block (4 rows x 256 floats), fc2
    for (int i = tid; i < NROWS * 384; i += NTHREADS) (&st[0][0])[i] = 0.f;
    for (int i = tid; i < NROWS * 128; i += NTHREADS) { (&c0s[0][0])[i] = 0.f; (&c1s[0][0])[i] = 0.f; }
    #pragma unroll
    for (int p = 0; p < 4; ++p) {
        int idx = tid + p * NTHREADS;          // [0, 1024)
        int r = idx >> 8, off = idx & 255;
        xs[r][off] = x[(rbase + r) * 256 + off];
    }
    if (tid < 128) fc2ws[tid] = fc2w[tid];
    if (tid < 2) fc2bs[tid] = fc2b[tid];
    __syncthreads();
    if (tid < 16) {
        int r = tid >> 2, k = tid & 3;
        st[r][k] = xs[r][k];
    }
    __syncthreads();

    // ---------------- LSTM encoder: layer wavefront ----------------
    // LSTM mapping: each thread -> gates {tid, tid+256}, all 4 rows.
    for (int t = 0; t <= SEQ; ++t) {
        {
            unsigned long long acc[2][4];
            if (t < SEQ) {
                #pragma unroll
                for (int i = 0; i < 2; ++i)
                    #pragma unroll
                    for (int j = 0; j < 4; ++j) acc[i][j] = 0ull;
                dotG<2, 512, 33>(S + OFF_W0, tid, &st[0][0], acc);
                #pragma unroll
                for (int i = 0; i < 2; ++i) {
                    float b = S[OFF_B0 + tid + 256 * i];
                    #pragma unroll
                    for (int j = 0; j < 4; ++j)
                        gb0[j][tid + 256 * i] = b + red2(acc[i][j]);
                }
            }
            if (t > 0) {
                #pragma unroll
                for (int i = 0; i < 2; ++i)
                    #pragma unroll
                    for (int j = 0; j < 4; ++j) acc[i][j] = 0ull;
                dotG<2, 512, 64>(S + OFF_W1, tid, &st[0][4], acc);
                #pragma unroll
                for (int i = 0; i < 2; ++i) {
                    float b = S[OFF_B1 + tid + 256 * i];
                    #pragma unroll
                    for (int j = 0; j < 4; ++j)
                        gb1[j][tid + 256 * i] = b + red2(acc[i][j]);
                }
            }
        }
        __syncthreads();

        // updates: h0(t), h1(t-1), stage x(t+1)
        if (t < SEQ) {
            #pragma unroll
            for (int p = 0; p < 2; ++p) {
                int idx = tid + p * NTHREADS;        // [0, 512)
                int r = idx >> 7, d = idx & 127;
                float gi = sigf(gb0[r][d]);
                float gf = sigf(gb0[r][128 + d]);
                float gg = tanhfast(gb0[r][256 + d]);
                float go = sigf(gb0[r][384 + d]);
                float cn = gf * c0s[r][d] + gi * gg;
                c0s[r][d] = cn;
                st[r][4 + d] = go * tanhfast(cn);
            }
        }
        if (t > 0) {
            #pragma unroll
            for (int p = 0; p < 2; ++p) {
                int idx = tid + p * NTHREADS;
                int r = idx >> 7, d = idx & 127;
                float gi = sigf(gb1[r][d]);
                float gf = sigf(gb1[r][128 + d]);
                float gg = tanhfast(gb1[r][256 + d]);
                float go = sigf(gb1[r][384 + d]);
                float cn = gf * c1s[r][d] + gi * gg;
                c1s[r][d] = cn;
                st[r][132 + d] = go * tanhfast(cn);
            }
        }
        if (t + 1 < SEQ && tid < 16) {
            int r = tid >> 2, k = tid & 3;
            st[r][k] = xs[r][(t + 1) * 4 + k];
        }
        __syncthreads();
    }

    // ---------------- bridge ----------------
    #pragma unroll
    for (int p = 0; p < 4; ++p) {
        int idx = tid + p * NTHREADS;          // [0, 1024)
        int l = idx >> 9;
        int rem = idx & 511;
        int r = rem >> 7, d = rem & 127;
        float acc = S[OFF_BB + d];
        acc = dot1<128, 32>(S + OFF_BR, d, &st[r][4 + 128 * l], acc);
        gb0[r][l * 128 + d] = tanhfast(acc);
    }
    __syncthreads();
    // restage: inp = h1(final), hd0 = hg0, hd1 = hg1
    {
        float inpv[2], g0v[2], g1v[2];
        #pragma unroll
        for (int p = 0; p < 2; ++p) {
            int idx = tid + p * NTHREADS;      // [0, 512)
            int r = idx >> 7, d = idx & 127;
            inpv[p] = st[r][132 + d];
            g0v[p] = gb0[r][d];
            g1v[p] = gb0[r][128 + d];
        }
        __syncthreads();
        #pragma unroll
        for (int p = 0; p < 2; ++p) {
            int idx = tid + p * NTHREADS;
            int r = idx >> 7, d = idx & 127;
            st[r][d] = inpv[p];
            st[r][128 + d] = g0v[p];
            st[r][256 + d] = g1v[p];
        }
    }
    __syncthreads();

    // ---------------- GRU decoder + folded head ----------------
    // roles:
    //  tid <128    : rz gates   NG=2 GW=256 (gates tid, tid+128), K4=64
    //  tid 128..191: n-in + n-hn NG=2 GW=128 (g=tid-128: g, g+64), K4=32+32
    //  tid 192..223: fc1(td-1)  NG=2 GW=64  (g=tid-192: g, g+32), K4=32
    //  tid 192..199: fc2(td-1) in phase G1
    for (int td = 0; td <= plen; ++td) {
        // --- phase G0: layer-0 gates + fc1(td-1) ---
        if (tid < 128) {
            if (td < plen) {
                unsigned long long acc[2][4];
                #pragma unroll
                for (int i = 0; i < 2; ++i)
                    #pragma unroll
                    for (int j = 0; j < 4; ++j) acc[i][j] = 0ull;
                dotG<2, 256, 64>(S + OFF_GRZ0, tid, &st[0][0], acc);
                #pragma unroll
                for (int i = 0; i < 2; ++i) {
                    float b = S[OFF_BRZ0 + tid + 128 * i];
                    #pragma unroll
                    for (int j = 0; j < 4; ++j)
                        gb0[j][tid + 128 * i] = b + red2(acc[i][j]);
                }
            }
        } else if (tid < 192) {
            if (td < plen) {
                int g = tid - 128;
                unsigned long long acc[2][4];
                #pragma unroll
                for (int i = 0; i < 2; ++i)
                    #pragma unroll
                    for (int j = 0; j < 4; ++j) acc[i][j] = 0ull;
                dotG<2, 128, 32>(S + OFF_WIN0, g, &st[0][0], acc);
                #pragma unroll
                for (int i = 0; i < 2; ++i) {
                    float b = S[OFF_BIN0 + g + 64 * i];
                    #pragma unroll
                    for (int j = 0; j < 4; ++j)
                        gb0[j][256 + g + 64 * i] = b + red2(acc[i][j]);
                }
                #pragma unroll
                for (int i = 0; i < 2; ++i)
                    #pragma unroll
                    for (int j = 0; j < 4; ++j) acc[i][j] = 0ull;
                dotG<2, 128, 32>(S + OFF_WHN0, g, &st[0][128], acc);
                #pragma unroll
                for (int i = 0; i < 2; ++i) {
                    float b = S[OFF_BHN0 + g + 64 * i];
                    #pragma unroll
                    for (int j = 0; j < 4; ++j)
                        gb0[j][384 + g + 64 * i] = b + red2(acc[i][j]);
                }
            }
        } else if (tid < 224) {
            if (td > 0) {
                int g = tid - 192;
                unsigned long long acc[2][4];
                #pragma unroll
                for (int i = 0; i < 2; ++i)
                    #pragma unroll
                    for (int j = 0; j < 4; ++j) acc[i][j] = 0ull;
                dotG<2, 64, 32>(S + OFF_FC1, g, &st[0][256], acc);
                #pragma unroll
                for (int i = 0; i < 2; ++i) {
                    float b = S[OFF_FC1B + g + 32 * i];
                    #pragma unroll
                    for (int j = 0; j < 4; ++j)
                        gbH[j][g + 32 * i] = fmaxf(b + red2(acc[i][j]), 0.f);
                }
            }
        }
        __syncthreads();

        // --- update h0 ---
        if (td < plen) {
            #pragma unroll
            for (int p = 0; p < 2; ++p) {
                int idx = tid + p * NTHREADS;   // [0, 512)
                int r = idx >> 7, d = idx & 127;
                float rv = sigf(gb0[r][d]);
                float zv = sigf(gb0[r][128 + d]);
                float nv = tanhfast(gb0[r][256 + d] + rv * gb0[r][384 + d]);
                float hold = st[r][128 + d];
                st[r][128 + d] = (1.f - zv) * nv + zv * hold;
            }
        }
        __syncthreads();

        // --- phase G1: layer-1 gates + fc2(td-1) + store ---
        if (tid < 128) {
            if (td < plen) {
                unsigned long long acc[2][4];
                #pragma unroll
                for (int i = 0; i < 2; ++i)
                    #pragma unroll
                    for (int j = 0; j < 4; ++j) acc[i][j] = 0ull;
                dotG<2, 256, 64>(S + OFF_GRZ1, tid, &st[0][128], acc);
                #pragma unroll
                for (int i = 0; i < 2; ++i) {
                    float b = S[OFF_BRZ1 + tid + 128 * i];
                    #pragma unroll
                    for (int j = 0; j < 4; ++j)
                        gb0[j][tid + 128 * i] = b + red2(acc[i][j]);
                }
            }
        } else if (tid < 192) {
            if (td < plen) {
                int g = tid - 128;
                unsigned long long acc[2][4];
                #pragma unroll
                for (int i = 0; i < 2; ++i)
                    #pragma unroll
                    for (int j = 0; j < 4; ++j) acc[i][j] = 0ull;
                dotG<2, 128, 32>(S + OFF_WIN1, g, &st[0][128], acc);
                #pragma unroll
                for (int i = 0; i < 2; ++i) {
                    float b = S[OFF_BIN1 + g + 64 * i];
                    #pragma unroll
                    for (int j = 0; j < 4; ++j)
                        gb0[j][256 + g + 64 * i] = b + red2(acc[i][j]);
                }
                #pragma unroll
                for (int i = 0; i < 2; ++i)
                    #pragma unroll
                    for (int j = 0; j < 4; ++j) acc[i][j] = 0ull;
                dotG<2, 128, 32>(S + OFF_WHN1, g, &st[0][256], acc);
                #pragma unroll
                for (int i = 0; i < 2; ++i) {
                    float b = S[OFF_BHN1 + g + 64 * i];
                    #pragma unroll
                    for (int j = 0; j < 4; ++j)
                        gb0[j][384 + g + 64 * i] = b + red2(acc[i][j]);
                }
            }
        } else if (tid < 200) {
            if (td > 0) {
                int lo = tid - 192;
                int r = lo >> 1, o = lo & 1;
                float a = fc2bs[o];
                #pragma unroll 8
                for (int k = 0; k < 64; ++k) a = fmaf(fc2ws[o * 64 + k], gbH[r][k], a);
                out[((rbase + r) * plen + (td - 1)) * 2 + o] = a;
            }
        }
        __syncthreads();

        // --- update h1, write next inp ---
        if (td < plen) {
            #pragma unroll
            for (int p = 0; p < 2; ++p) {
                int idx = tid + p * NTHREADS;
                int r = idx >> 7, d = idx & 127;
                float rv = sigf(gb0[r][d]);
                float zv = sigf(gb0[r][128 + d]);
                float nv = tanhfast(gb0[r][256 + d] + rv * gb0[r][384 + d]);
                float hold = st[r][256 + d];
                float hnew = (1.f - zv) * nv + zv * hold;
                st[r][256 + d] = hnew;
                st[r][d] = hnew;
            }
        }
        __syncthreads();
    }
}

// ---------------------------------------------------------------------------
// launch
// ---------------------------------------------------------------------------
extern "C" void kernel_launch(void* const* d_in, const int* in_sizes, int n_in,
                              void* d_out, int out_size)
{
    const float* x        = (const float*)d_in[0];
    const int*   pred_len = (const int*)  d_in[1];
    const float* wih0  = (const float*)d_in[2];
    const float* whh0  = (const float*)d_in[3];
    const float* bih0  = (const float*)d_in[4];
    const float* bhh0  = (const float*)d_in[5];
    const float* wih1  = (const float*)d_in[6];
    const float* whh1  = (const float*)d_in[7];
    const float* bih1  = (const float*)d_in[8];
    const float* bhh1  = (const float*)d_in[9];
    const float* gwih0 = (const float*)d_in[10];
    const float* gwhh0 = (const float*)d_in[11];
    const float* gbih0 = (const float*)d_in[12];
    const float* gbhh0 = (const float*)d_in[13];
    const float* gwih1 = (const float*)d_in[14];
    const float* gwhh1 = (const float*)d_in[15];
    const float* gbih1 = (const float*)d_in[16];
    const float* gbhh1 = (const float*)d_in[17];
    const float* brw   = (const float*)d_in[18];
    const float* brb   = (const float*)d_in[19];
    const float* fc1w  = (const float*)d_in[20];
    const float* fc1b  = (const float*)d_in[21];
    const float* fc2w  = (const float*)d_in[22];
    const float* fc2b  = (const float*)d_in[23];
    float* out = (float*)d_out;

    static bool attr_set = false;
    if (!attr_set) {
        cudaFuncSetAttribute(fused_kernel,
                             cudaFuncAttributeMaxDynamicSharedMemorySize, SMEM_BYTES);
        attr_set = true;
    }

    int prep_blocks = (SCRATCH_TOTAL + 255) / 256;
    prep_kernel<<<prep_blocks, 256>>>(wih0, whh0, bih0, bhh0,
                                      wih1, whh1, bih1, bhh1,
                                      gwih0, gwhh0, gbih0, gbhh0,
                                      gwih1, gwhh1, gbih1, gbhh1,
                                      brw, brb, fc1w, fc1b);
    fused_kernel<<<NBLOCKS, NTHREADS, SMEM_BYTES>>>(x, pred_len, fc2w, fc2b, out);
}

// round 7
// speedup vs baseline: 1.0332x; 1.0332x over previous
#include <cuda_runtime.h>
#include <cuda_bf16.h>

// ---------------------------------------------------------------------------
// Fused LSTM(2)->bridge->GRU(2, autoregressive)->MLP predictor.
// B=2048, H=128, S=64. 256 blocks x 8 rows, 128 threads.
// Tile: 4 gates x 8 rows per thread (fma.rn.f32x2 packed over k),
// manual weight prefetch. LSTM layer-wavefront; GRU head folded.
// ---------------------------------------------------------------------------

#define NROWS 8
#define NTHREADS 128
#define NBLOCKS 256   // 2048 / 8
#define SEQ 64
#define H 128

// ----- scratch layout (floats), identical to validated layout -----
#define OFF_W0    0
#define OFF_W1    67584
#define OFF_GRZ0  198656
#define OFF_GRZ1  264192
#define OFF_WIN0  329728
#define OFF_WHN0  346112
#define OFF_WIN1  362496
#define OFF_WHN1  378880
#define OFF_BR    395264
#define OFF_FC1   411648
#define OFF_B0    419840
#define OFF_B1    420352
#define OFF_BRZ0  420864
#define OFF_BRZ1  421120
#define OFF_BIN0  421376
#define OFF_BHN0  421504
#define OFF_BIN1  421632
#define OFF_BHN1  421760
#define OFF_BB    421888
#define OFF_FC1B  422016
#define SCRATCH_TOTAL 422080

__device__ __align__(16) float g_scratch[SCRATCH_TOTAL];

// dynamic smem layout (floats)
#define SM_ST   0                     // st[8][384]
#define SM_C0   (NROWS*384)           // c0s[8][128]
#define SM_C1   (SM_C0 + NROWS*128)   // c1s[8][128]
#define SM_GB0  (SM_C1 + NROWS*128)   // gb0[8][512]
#define SM_GB1  (SM_GB0 + NROWS*512)  // gb1[8][512]
#define SM_GBH  (SM_GB1 + NROWS*512)  // gbH[8][64]
#define SM_TOTAL (SM_GBH + NROWS*64)  // 13824 floats = 55296 bytes
#define SMEM_BYTES (SM_TOTAL * 4)

// ---------------------------------------------------------------------------
// Prep kernel (unchanged, validated)
// ---------------------------------------------------------------------------
__global__ void prep_kernel(
    const float* __restrict__ wih0, const float* __restrict__ whh0,
    const float* __restrict__ bih0, const float* __restrict__ bhh0,
    const float* __restrict__ wih1, const float* __restrict__ whh1,
    const float* __restrict__ bih1, const float* __restrict__ bhh1,
    const float* __restrict__ gwih0, const float* __restrict__ gwhh0,
    const float* __restrict__ gbih0, const float* __restrict__ gbhh0,
    const float* __restrict__ gwih1, const float* __restrict__ gwhh1,
    const float* __restrict__ gbih1, const float* __restrict__ gbhh1,
    const float* __restrict__ brw,  const float* __restrict__ brb,
    const float* __restrict__ fc1w, const float* __restrict__ fc1b)
{
    int idx = blockIdx.x * blockDim.x + threadIdx.x;
    if (idx >= SCRATCH_TOTAL) return;
    float v = 0.0f;

    if (idx < OFF_W1) {
        int i = idx - OFF_W0;
        int kk = i & 3; int j = i >> 2; int g = j & 511; int k4 = j >> 9;
        int k = 4*k4 + kk;
        v = (k < 4) ? wih0[g*4 + k] : whh0[g*128 + (k - 4)];
    } else if (idx < OFF_GRZ0) {
        int i = idx - OFF_W1;
        int kk = i & 3; int j = i >> 2; int g = j & 511; int k4 = j >> 9;
        int k = 4*k4 + kk;
        v = (k < 128) ? wih1[g*128 + k] : whh1[g*128 + (k - 128)];
    } else if (idx < OFF_GRZ1) {
        int i = idx - OFF_GRZ0;
        int kk = i & 3; int j = i >> 2; int g = j & 255; int k4 = j >> 8;
        int k = 4*k4 + kk;
        v = (k < 128) ? gwih0[g*128 + k] : gwhh0[g*128 + (k - 128)];
    } else if (idx < OFF_WIN0) {
        int i = idx - OFF_GRZ1;
        int kk = i & 3; int j = i >> 2; int g = j & 255; int k4 = j >> 8;
        int k = 4*k4 + kk;
        v = (k < 128) ? gwih1[g*128 + k] : gwhh1[g*128 + (k - 128)];
    } else if (idx < OFF_WHN0) {
        int i = idx - OFF_WIN0;
        int kk = i & 3; int j = i >> 2; int g = j & 127; int k4 = j >> 7;
        v = gwih0[(256 + g)*128 + 4*k4 + kk];
    } else if (idx < OFF_WIN1) {
        int i = idx - OFF_WHN0;
        int kk = i & 3; int j = i >> 2; int g = j & 127; int k4 = j >> 7;
        v = gwhh0[(256 + g)*128 + 4*k4 + kk];
    } else if (idx < OFF_WHN1) {
        int i = idx - OFF_WIN1;
        int kk = i & 3; int j = i >> 2; int g = j & 127; int k4 = j >> 7;
        v = gwih1[(256 + g)*128 + 4*k4 + kk];
    } else if (idx < OFF_BR) {
        int i = idx - OFF_WHN1;
        int kk = i & 3; int j = i >> 2; int g = j & 127; int k4 = j >> 7;
        v = gwhh1[(256 + g)*128 + 4*k4 + kk];
    } else if (idx < OFF_FC1) {
        int i = idx - OFF_BR;
        int kk = i & 3; int j = i >> 2; int g = j & 127; int k4 = j >> 7;
        v = brw[g*128 + 4*k4 + kk];
    } else if (idx < OFF_B0) {
        int i = idx - OFF_FC1;
        int kk = i & 3; int j = i >> 2; int g = j & 63; int k4 = j >> 6;
        v = fc1w[g*128 + 4*k4 + kk];
    } else if (idx < OFF_B1)   { int i = idx - OFF_B0;   v = bih0[i] + bhh0[i]; }
    else if (idx < OFF_BRZ0)   { int i = idx - OFF_B1;   v = bih1[i] + bhh1[i]; }
    else if (idx < OFF_BRZ1)   { int i = idx - OFF_BRZ0; v = gbih0[i] + gbhh0[i]; }
    else if (idx < OFF_BIN0)   { int i = idx - OFF_BRZ1; v = gbih1[i] + gbhh1[i]; }
    else if (idx < OFF_BHN0)   { int i = idx - OFF_BIN0; v = gbih0[256 + i]; }
    else if (idx < OFF_BIN1)   { int i = idx - OFF_BHN0; v = gbhh0[256 + i]; }
    else if (idx < OFF_BHN1)   { int i = idx - OFF_BIN1; v = gbih1[256 + i]; }
    else if (idx < OFF_BB)     { int i = idx - OFF_BHN1; v = gbhh1[256 + i]; }
    else if (idx < OFF_FC1B)   { int i = idx - OFF_BB;   v = brb[i]; }
    else                       { int i = idx - OFF_FC1B; v = fc1b[i]; }

    g_scratch[idx] = v;
}

// ---------------------------------------------------------------------------
// Activations (fast-math)
// ---------------------------------------------------------------------------
__device__ __forceinline__ float sigf(float x) {
    x = fminf(fmaxf(x, -30.f), 30.f);
    return __fdividef(1.f, 1.f + __expf(-x));
}
__device__ __forceinline__ float tanhfast(float x) {
    x = fminf(fmaxf(x, -15.f), 15.f);
    float e = __expf(2.f * x);
    return 1.f - __fdividef(2.f, e + 1.f);
}

// ---------------------------------------------------------------------------
// Packed f32x2 FMA
// ---------------------------------------------------------------------------
__device__ __forceinline__ void ffma2(unsigned long long& d,
                                      unsigned long long a,
                                      unsigned long long b) {
    asm("fma.rn.f32x2 %0, %1, %2, %0;" : "+l"(d) : "l"(a), "l"(b));
}
__device__ __forceinline__ float red2(unsigned long long a) {
    float lo = __uint_as_float((unsigned)(a & 0xffffffffull));
    float hi = __uint_as_float((unsigned)(a >> 32));
    return lo + hi;
}

// ---------------------------------------------------------------------------
// Tiled dot: NG gates (stride GW/NG) x 8 rows, f32x2 over k, with manual
// one-deep weight prefetch (covers L2 latency even at low warp residency).
// ---------------------------------------------------------------------------
template<int NG, int GW, int K4>
__device__ __forceinline__ void dotG8(const float* __restrict__ wbase, int g0,
                                      const float* __restrict__ stp,
                                      unsigned long long acc[NG][8])
{
    const ulonglong2* wq = reinterpret_cast<const ulonglong2*>(wbase);
    ulonglong2 w[NG];
    #pragma unroll
    for (int i = 0; i < NG; ++i)
        w[i] = __ldg(&wq[g0 + i * (GW / NG)]);
    #pragma unroll 2
    for (int k4 = 0; k4 < K4; ++k4) {
        ulonglong2 wc[NG];
        #pragma unroll
        for (int i = 0; i < NG; ++i) wc[i] = w[i];
        if (k4 + 1 < K4) {
            #pragma unroll
            for (int i = 0; i < NG; ++i)
                w[i] = __ldg(&wq[(k4 + 1) * GW + g0 + i * (GW / NG)]);
        }
        #pragma unroll
        for (int j = 0; j < 8; ++j) {
            ulonglong2 s = *reinterpret_cast<const ulonglong2*>(stp + j * 384 + 4 * k4);
            #pragma unroll
            for (int i = 0; i < NG; ++i) {
                ffma2(acc[i][j], wc[i].x, s.x);
                ffma2(acc[i][j], wc[i].y, s.y);
            }
        }
    }
}

// scalar single-row dot (bridge)
template<int GW, int K4>
__device__ __forceinline__ float dot1(const float* __restrict__ wbase, int g,
                                      const float* __restrict__ srow, float acc)
{
    const float4* w4 = reinterpret_cast<const float4*>(wbase);
    const float4* s4 = reinterpret_cast<const float4*>(srow);
    #pragma unroll 4
    for (int k4 = 0; k4 < K4; ++k4) {
        float4 w = __ldg(&w4[k4 * GW + g]);
        float4 s = s4[k4];
        acc = fmaf(w.x, s.x, acc);
        acc = fmaf(w.y, s.y, acc);
        acc = fmaf(w.z, s.z, acc);
        acc = fmaf(w.w, s.w, acc);
    }
    return acc;
}

#define ZACC(A, NI) { _Pragma("unroll") for (int i = 0; i < NI; ++i) \
                      _Pragma("unroll") for (int j = 0; j < 8; ++j) A[i][j] = 0ull; }

// ---------------------------------------------------------------------------
// Main fused kernel: 128 threads, 8 rows, 4g x 8r tile
// ---------------------------------------------------------------------------
__global__ void __launch_bounds__(NTHREADS, 2)
fused_kernel(const float* __restrict__ x, const int* __restrict__ plen_p,
             const float* __restrict__ fc2w, const float* __restrict__ fc2b,
             float* __restrict__ out)
{
    extern __shared__ float sm[];
    float (*st)[384]  = (float (*)[384])(sm + SM_ST);
    float (*c0s)[128] = (float (*)[128])(sm + SM_C0);
    float (*c1s)[128] = (float (*)[128])(sm + SM_C1);
    float (*gb0)[512] = (float (*)[512])(sm + SM_GB0);
    float (*gb1)[512] = (float (*)[512])(sm + SM_GB1);
    float (*gbH)[64]  = (float (*)[64])(sm + SM_GBH);
    __shared__ float fc2ws[128];
    __shared__ float fc2bs[2];

    const int tid = threadIdx.x;
    const int rbase = blockIdx.x * NROWS;
    const float* S = g_scratch;
    const int plen = plen_p[0];

    // init
    for (int i = tid; i < NROWS * 384; i += NTHREADS) (&st[0][0])[i] = 0.f;
    for (int i = tid; i < NROWS * 128; i += NTHREADS) { (&c0s[0][0])[i] = 0.f; (&c1s[0][0])[i] = 0.f; }
    fc2ws[tid] = fc2w[tid];
    if (tid < 2) fc2bs[tid] = fc2b[tid];
    __syncthreads();
    if (tid < 32) {
        int r = tid >> 2, k = tid & 3;
        st[r][k] = x[(rbase + r) * 256 + k];
    }
    __syncthreads();

    // ---------------- LSTM encoder: layer wavefront ----------------
    // Each thread: gates {tid, tid+128, tid+256, tid+384}, all 8 rows.
    for (int t = 0; t <= SEQ; ++t) {
        {
            unsigned long long acc[4][8];
            if (t < SEQ) {
                ZACC(acc, 4);
                dotG8<4, 512, 33>(S + OFF_W0, tid, &st[0][0], acc);
                #pragma unroll
                for (int i = 0; i < 4; ++i) {
                    float b = S[OFF_B0 + tid + 128 * i];
                    #pragma unroll
                    for (int j = 0; j < 8; ++j)
                        gb0[j][tid + 128 * i] = b + red2(acc[i][j]);
                }
            }
            if (t > 0) {
                ZACC(acc, 4);
                dotG8<4, 512, 64>(S + OFF_W1, tid, &st[0][4], acc);
                #pragma unroll
                for (int i = 0; i < 4; ++i) {
                    float b = S[OFF_B1 + tid + 128 * i];
                    #pragma unroll
                    for (int j = 0; j < 8; ++j)
                        gb1[j][tid + 128 * i] = b + red2(acc[i][j]);
                }
            }
        }
        __syncthreads();

        // updates: h0(t), h1(t-1), stage x(t+1)
        if (t < SEQ) {
            #pragma unroll
            for (int p = 0; p < 8; ++p) {
                int idx = tid + p * NTHREADS;        // [0, 1024)
                int r = idx >> 7, d = idx & 127;
                float gi = sigf(gb0[r][d]);
                float gf = sigf(gb0[r][128 + d]);
                float gg = tanhfast(gb0[r][256 + d]);
                float go = sigf(gb0[r][384 + d]);
                float cn = gf * c0s[r][d] + gi * gg;
                c0s[r][d] = cn;
                st[r][4 + d] = go * tanhfast(cn);
            }
        }
        if (t > 0) {
            #pragma unroll
            for (int p = 0; p < 8; ++p) {
                int idx = tid + p * NTHREADS;
                int r = idx >> 7, d = idx & 127;
                float gi = sigf(gb1[r][d]);
                float gf = sigf(gb1[r][128 + d]);
                float gg = tanhfast(gb1[r][256 + d]);
                float go = sigf(gb1[r][384 + d]);
                float cn = gf * c1s[r][d] + gi * gg;
                c1s[r][d] = cn;
                st[r][132 + d] = go * tanhfast(cn);
            }
        }
        if (t + 1 < SEQ && tid < 32) {
            int r = tid >> 2, k = tid & 3;
            st[r][k] = x[(rbase + r) * 256 + (t + 1) * 4 + k];
        }
        __syncthreads();
    }

    // ---------------- bridge ----------------
    #pragma unroll
    for (int p = 0; p < 16; ++p) {
        int idx = tid + p * NTHREADS;          // [0, 2048)
        int l = idx >> 10;
        int rem = idx & 1023;
        int r = rem >> 7, d = rem & 127;
        float acc = S[OFF_BB + d];
        acc = dot1<128, 32>(S + OFF_BR, d, &st[r][4 + 128 * l], acc);
        gb0[r][l * 128 + d] = tanhfast(acc);
    }
    __syncthreads();
    // restage: inp = h1(final), hd0 = hg0, hd1 = hg1
    {
        float inpv[8], g0v[8], g1v[8];
        #pragma unroll
        for (int p = 0; p < 8; ++p) {
            int idx = tid + p * NTHREADS;      // [0, 1024)
            int r = idx >> 7, d = idx & 127;
            inpv[p] = st[r][132 + d];
            g0v[p] = gb0[r][d];
            g1v[p] = gb0[r][128 + d];
        }
        __syncthreads();
        #pragma unroll
        for (int p = 0; p < 8; ++p) {
            int idx = tid + p * NTHREADS;
            int r = idx >> 7, d = idx & 127;
            st[r][d] = inpv[p];
            st[r][128 + d] = g0v[p];
            st[r][256 + d] = g1v[p];
        }
    }
    __syncthreads();

    // ---------------- GRU decoder + folded head ----------------
    // roles (128 threads, 8 rows each):
    //  tid <64   : rz gates   NG=4 GW=256 (g = tid, +64 stride), K4=64
    //  tid 64..95: n-in+n-hn  NG=4 GW=128 (g = tid-64, +32 stride), K4=32+32
    //  tid 96..127: fc1(td-1) NG=2 GW=64  (g = tid-96, +32 stride), K4=32
    //  tid 96..111: fc2(td-1) in phase G1
    for (int td = 0; td <= plen; ++td) {
        // --- phase G0: layer-0 gates + fc1(td-1) ---
        if (tid < 64) {
            if (td < plen) {
                unsigned long long acc[4][8];
                ZACC(acc, 4);
                dotG8<4, 256, 64>(S + OFF_GRZ0, tid, &st[0][0], acc);
                #pragma unroll
                for (int i = 0; i < 4; ++i) {
                    float b = S[OFF_BRZ0 + tid + 64 * i];
                    #pragma unroll
                    for (int j = 0; j < 8; ++j)
                        gb0[j][tid + 64 * i] = b + red2(acc[i][j]);
                }
            }
        } else if (tid < 96) {
            if (td < plen) {
                int g = tid - 64;
                unsigned long long acc[4][8];
                ZACC(acc, 4);
                dotG8<4, 128, 32>(S + OFF_WIN0, g, &st[0][0], acc);
                #pragma unroll
                for (int i = 0; i < 4; ++i) {
                    float b = S[OFF_BIN0 + g + 32 * i];
                    #pragma unroll
                    for (int j = 0; j < 8; ++j)
                        gb0[j][256 + g + 32 * i] = b + red2(acc[i][j]);
                }
                ZACC(acc, 4);
                dotG8<4, 128, 32>(S + OFF_WHN0, g, &st[0][128], acc);
                #pragma unroll
                for (int i = 0; i < 4; ++i) {
                    float b = S[OFF_BHN0 + g + 32 * i];
                    #pragma unroll
                    for (int j = 0; j < 8; ++j)
                        gb0[j][384 + g + 32 * i] = b + red2(acc[i][j]);
                }
            }
        } else {
            if (td > 0) {
                int g = tid - 96;
                unsigned long long acc[2][8];
                ZACC(acc, 2);
                dotG8<2, 64, 32>(S + OFF_FC1, g, &st[0][256], acc);
                #pragma unroll
                for (int i = 0; i < 2; ++i) {
                    float b = S[OFF_FC1B + g + 32 * i];
                    #pragma unroll
                    for (int j = 0; j < 8; ++j)
                        gbH[j][g + 32 * i] = fmaxf(b + red2(acc[i][j]), 0.f);
                }
            }
        }
        __syncthreads();

        // --- update h0 ---
        if (td < plen) {
            #pragma unroll
            for (int p = 0; p < 8; ++p) {
                int idx = tid + p * NTHREADS;   // [0, 1024)
                int r = idx >> 7, d = idx & 127;
                float rv = sigf(gb0[r][d]);
                float zv = sigf(gb0[r][128 + d]);
                float nv = tanhfast(gb0[r][256 + d] + rv * gb0[r][384 + d]);
                float hold = st[r][128 + d];
                st[r][128 + d] = (1.f - zv) * nv + zv * hold;
            }
        }
        __syncthreads();

        // --- phase G1: layer-1 gates + fc2(td-1) + store ---
        if (tid < 64) {
            if (td < plen) {
                unsigned long long acc[4][8];
                ZACC(acc, 4);
                dotG8<4, 256, 64>(S + OFF_GRZ1, tid, &st[0][128], acc);
                #pragma unroll
                for (int i = 0; i < 4; ++i) {
                    float b = S[OFF_BRZ1 + tid + 64 * i];
                    #pragma unroll
                    for (int j = 0; j < 8; ++j)
                        gb0[j][tid + 64 * i] = b + red2(acc[i][j]);
                }
            }
        } else if (tid < 96) {
            if (td < plen) {
                int g = tid - 64;
                unsigned long long acc[4][8];
                ZACC(acc, 4);
                dotG8<4, 128, 32>(S + OFF_WIN1, g, &st[0][128], acc);
                #pragma unroll
                for (int i = 0; i < 4; ++i) {
                    float b = S[OFF_BIN1 + g + 32 * i];
                    #pragma unroll
                    for (int j = 0; j < 8; ++j)
                        gb0[j][256 + g + 32 * i] = b + red2(acc[i][j]);
                }
                ZACC(acc, 4);
                dotG8<4, 128, 32>(S + OFF_WHN1, g, &st[0][256], acc);
                #pragma unroll
                for (int i = 0; i < 4; ++i) {
                    float b = S[OFF_BHN1 + g + 32 * i];
                    #pragma unroll
                    for (int j = 0; j < 8; ++j)
                        gb0[j][384 + g + 32 * i] = b + red2(acc[i][j]);
                }
            }
        } else if (tid < 112) {
            if (td > 0) {
                int lo = tid - 96;
                int r = lo >> 1, o = lo & 1;
                float a = fc2bs[o];
                #pragma unroll 8
                for (int k = 0; k < 64; ++k) a = fmaf(fc2ws[o * 64 + k], gbH[r][k], a);
                out[((rbase + r) * plen + (td - 1)) * 2 + o] = a;
            }
        }
        __syncthreads();

        // --- update h1, write next inp ---
        if (td < plen) {
            #pragma unroll
            for (int p = 0; p < 8; ++p) {
                int idx = tid + p * NTHREADS;
                int r = idx >> 7, d = idx & 127;
                float rv = sigf(gb0[r][d]);
                float zv = sigf(gb0[r][128 + d]);
                float nv = tanhfast(gb0[r][256 + d] + rv * gb0[r][384 + d]);
                float hold = st[r][256 + d];
                float hnew = (1.f - zv) * nv + zv * hold;
                st[r][256 + d] = hnew;
                st[r][d] = hnew;
            }
        }
        __syncthreads();
    }
}

// ---------------------------------------------------------------------------
// launch
// ---------------------------------------------------------------------------
extern "C" void kernel_launch(void* const* d_in, const int* in_sizes, int n_in,
                              void* d_out, int out_size)
{
    const float* x        = (const float*)d_in[0];
    const int*   pred_len = (const int*)  d_in[1];
    const float* wih0  = (const float*)d_in[2];
    const float* whh0  = (const float*)d_in[3];
    const float* bih0  = (const float*)d_in[4];
    const float* bhh0  = (const float*)d_in[5];
    const float* wih1  = (const float*)d_in[6];
    const float* whh1  = (const float*)d_in[7];
    const float* bih1  = (const float*)d_in[8];
    const float* bhh1  = (const float*)d_in[9];
    const float* gwih0 = (const float*)d_in[10];
    const float* gwhh0 = (const float*)d_in[11];
    const float* gbih0 = (const float*)d_in[12];
    const float* gbhh0 = (const float*)d_in[13];
    const float* gwih1 = (const float*)d_in[14];
    const float* gwhh1 = (const float*)d_in[15];
    const float* gbih1 = (const float*)d_in[16];
    const float* gbhh1 = (const float*)d_in[17];
    const float* brw   = (const float*)d_in[18];
    const float* brb   = (const float*)d_in[19];
    const float* fc1w  = (const float*)d_in[20];
    const float* fc1b  = (const float*)d_in[21];
    const float* fc2w  = (const float*)d_in[22];
    const float* fc2b  = (const float*)d_in[23];
    float* out = (float*)d_out;

    static bool attr_set = false;
    if (!attr_set) {
        cudaFuncSetAttribute(fused_kernel,
                             cudaFuncAttributeMaxDynamicSharedMemorySize, SMEM_BYTES);
        attr_set = true;
    }

    int prep_blocks = (SCRATCH_TOTAL + 255) / 256;
    prep_kernel<<<prep_blocks, 256>>>(wih0, whh0, bih0, bhh0,
                                      wih1, whh1, bih1, bhh1,
                                      gwih0, gwhh0, gbih0, gbhh0,
                                      gwih1, gwhh1, gbih1, gbhh1,
                                      brw, brb, fc1w, fc1b);
    fused_kernel<<<NBLOCKS, NTHREADS, SMEM_BYTES>>>(x, pred_len, fc2w, fc2b, out);
}

// round 8
// speedup vs baseline: 1.0337x; 1.0005x over previous
#include <cuda_runtime.h>
#include <cuda_bf16.h>

// ---------------------------------------------------------------------------
// Fused LSTM(2)->bridge->GRU(2, autoregressive)->MLP predictor.
// B=2048, H=128, S=64. 256 blocks x 8 rows, 128 threads.
// Tile: 4 gates x 8 rows per thread (fma.rn.f32x2 packed over k),
// manual weight prefetch. LSTM layer-wavefront; GRU head folded.
// ---------------------------------------------------------------------------

#define NROWS 8
#define NTHREADS 128
#define NBLOCKS 256   // 2048 / 8
#define SEQ 64
#define H 128

// ----- scratch layout (floats), identical to validated layout -----
#define OFF_W0    0
#define OFF_W1    67584
#define OFF_GRZ0  198656
#define OFF_GRZ1  264192
#define OFF_WIN0  329728
#define OFF_WHN0  346112
#define OFF_WIN1  362496
#define OFF_WHN1  378880
#define OFF_BR    395264
#define OFF_FC1   411648
#define OFF_B0    419840
#define OFF_B1    420352
#define OFF_BRZ0  420864
#define OFF_BRZ1  421120
#define OFF_BIN0  421376
#define OFF_BHN0  421504
#define OFF_BIN1  421632
#define OFF_BHN1  421760
#define OFF_BB    421888
#define OFF_FC1B  422016
#define SCRATCH_TOTAL 422080

__device__ __align__(16) float g_scratch[SCRATCH_TOTAL];

// dynamic smem layout (floats)
#define SM_ST   0                     // st[8][384]
#define SM_C0   (NROWS*384)           // c0s[8][128]
#define SM_C1   (SM_C0 + NROWS*128)   // c1s[8][128]
#define SM_GB0  (SM_C1 + NROWS*128)   // gb0[8][512]
#define SM_GB1  (SM_GB0 + NROWS*512)  // gb1[8][512]
#define SM_GBH  (SM_GB1 + NROWS*512)  // gbH[8][64]
#define SM_TOTAL (SM_GBH + NROWS*64)  // 13824 floats = 55296 bytes
#define SMEM_BYTES (SM_TOTAL * 4)

// ---------------------------------------------------------------------------
// Prep kernel (unchanged, validated)
// ---------------------------------------------------------------------------
__global__ void prep_kernel(
    const float* __restrict__ wih0, const float* __restrict__ whh0,
    const float* __restrict__ bih0, const float* __restrict__ bhh0,
    const float* __restrict__ wih1, const float* __restrict__ whh1,
    const float* __restrict__ bih1, const float* __restrict__ bhh1,
    const float* __restrict__ gwih0, const float* __restrict__ gwhh0,
    const float* __restrict__ gbih0, const float* __restrict__ gbhh0,
    const float* __restrict__ gwih1, const float* __restrict__ gwhh1,
    const float* __restrict__ gbih1, const float* __restrict__ gbhh1,
    const float* __restrict__ brw,  const float* __restrict__ brb,
    const float* __restrict__ fc1w, const float* __restrict__ fc1b)
{
    int idx = blockIdx.x * blockDim.x + threadIdx.x;
    if (idx >= SCRATCH_TOTAL) return;
    float v = 0.0f;

    if (idx < OFF_W1) {
        int i = idx - OFF_W0;
        int kk = i & 3; int j = i >> 2; int g = j & 511; int k4 = j >> 9;
        int k = 4*k4 + kk;
        v = (k < 4) ? wih0[g*4 + k] : whh0[g*128 + (k - 4)];
    } else if (idx < OFF_GRZ0) {
        int i = idx - OFF_W1;
        int kk = i & 3; int j = i >> 2; int g = j & 511; int k4 = j >> 9;
        int k = 4*k4 + kk;
        v = (k < 128) ? wih1[g*128 + k] : whh1[g*128 + (k - 128)];
    } else if (idx < OFF_GRZ1) {
        int i = idx - OFF_GRZ0;
        int kk = i & 3; int j = i >> 2; int g = j & 255; int k4 = j >> 8;
        int k = 4*k4 + kk;
        v = (k < 128) ? gwih0[g*128 + k] : gwhh0[g*128 + (k - 128)];
    } else if (idx < OFF_WIN0) {
        int i = idx - OFF_GRZ1;
        int kk = i & 3; int j = i >> 2; int g = j & 255; int k4 = j >> 8;
        int k = 4*k4 + kk;
        v = (k < 128) ? gwih1[g*128 + k] : gwhh1[g*128 + (k - 128)];
    } else if (idx < OFF_WHN0) {
        int i = idx - OFF_WIN0;
        int kk = i & 3; int j = i >> 2; int g = j & 127; int k4 = j >> 7;
        v = gwih0[(256 + g)*128 + 4*k4 + kk];
    } else if (idx < OFF_WIN1) {
        int i = idx - OFF_WHN0;
        int kk = i & 3; int j = i >> 2; int g = j & 127; int k4 = j >> 7;
        v = gwhh0[(256 + g)*128 + 4*k4 + kk];
    } else if (idx < OFF_WHN1) {
        int i = idx - OFF_WIN1;
        int kk = i & 3; int j = i >> 2; int g = j & 127; int k4 = j >> 7;
        v = gwih1[(256 + g)*128 + 4*k4 + kk];
    } else if (idx < OFF_BR) {
        int i = idx - OFF_WHN1;
        int kk = i & 3; int j = i >> 2; int g = j & 127; int k4 = j >> 7;
        v = gwhh1[(256 + g)*128 + 4*k4 + kk];
    } else if (idx < OFF_FC1) {
        int i = idx - OFF_BR;
        int kk = i & 3; int j = i >> 2; int g = j & 127; int k4 = j >> 7;
        v = brw[g*128 + 4*k4 + kk];
    } else if (idx < OFF_B0) {
        int i = idx - OFF_FC1;
        int kk = i & 3; int j = i >> 2; int g = j & 63; int k4 = j >> 6;
        v = fc1w[g*128 + 4*k4 + kk];
    } else if (idx < OFF_B1)   { int i = idx - OFF_B0;   v = bih0[i] + bhh0[i]; }
    else if (idx < OFF_BRZ0)   { int i = idx - OFF_B1;   v = bih1[i] + bhh1[i]; }
    else if (idx < OFF_BRZ1)   { int i = idx - OFF_BRZ0; v = gbih0[i] + gbhh0[i]; }
    else if (idx < OFF_BIN0)   { int i = idx - OFF_BRZ1; v = gbih1[i] + gbhh1[i]; }
    else if (idx < OFF_BHN0)   { int i = idx - OFF_BIN0; v = gbih0[256 + i]; }
    else if (idx < OFF_BIN1)   { int i = idx - OFF_BHN0; v = gbhh0[256 + i]; }
    else if (idx < OFF_BHN1)   { int i = idx - OFF_BIN1; v = gbih1[256 + i]; }
    else if (idx < OFF_BB)     { int i = idx - OFF_BHN1; v = gbhh1[256 + i]; }
    else if (idx < OFF_FC1B)   { int i = idx - OFF_BB;   v = brb[i]; }
    else                       { int i = idx - OFF_FC1B; v = fc1b[i]; }

    g_scratch[idx] = v;
}

// ---------------------------------------------------------------------------
// Activations (fast-math)
// ---------------------------------------------------------------------------
__device__ __forceinline__ float sigf(float x) {
    x = fminf(fmaxf(x, -30.f), 30.f);
    return __fdividef(1.f, 1.f + __expf(-x));
}
__device__ __forceinline__ float tanhfast(float x) {
    x = fminf(fmaxf(x, -15.f), 15.f);
    float e = __expf(2.f * x);
    return 1.f - __fdividef(2.f, e + 1.f);
}

// ---------------------------------------------------------------------------
// Packed f32x2 FMA
// ---------------------------------------------------------------------------
__device__ __forceinline__ void ffma2(unsigned long long& d,
                                      unsigned long long a,
                                      unsigned long long b) {
    asm("fma.rn.f32x2 %0, %1, %2, %0;" : "+l"(d) : "l"(a), "l"(b));
}
__device__ __forceinline__ float red2(unsigned long long a) {
    float lo = __uint_as_float((unsigned)(a & 0xffffffffull));
    float hi = __uint_as_float((unsigned)(a >> 32));
    return lo + hi;
}

// ---------------------------------------------------------------------------
// Tiled dot: NG gates (stride GW/NG) x 8 rows, f32x2 over k, with manual
// one-deep weight prefetch (covers L2 latency even at low warp residency).
// ---------------------------------------------------------------------------
template<int NG, int GW, int K4>
__device__ __forceinline__ void dotG8(const float* __restrict__ wbase, int g0,
                                      const float* __restrict__ stp,
                                      unsigned long long acc[NG][8])
{
    const ulonglong2* wq = reinterpret_cast<const ulonglong2*>(wbase);
    ulonglong2 w[NG];
    #pragma unroll
    for (int i = 0; i < NG; ++i)
        w[i] = __ldg(&wq[g0 + i * (GW / NG)]);
    #pragma unroll 2
    for (int k4 = 0; k4 < K4; ++k4) {
        ulonglong2 wc[NG];
        #pragma unroll
        for (int i = 0; i < NG; ++i) wc[i] = w[i];
        if (k4 + 1 < K4) {
            #pragma unroll
            for (int i = 0; i < NG; ++i)
                w[i] = __ldg(&wq[(k4 + 1) * GW + g0 + i * (GW / NG)]);
        }
        #pragma unroll
        for (int j = 0; j < 8; ++j) {
            ulonglong2 s = *reinterpret_cast<const ulonglong2*>(stp + j * 384 + 4 * k4);
            #pragma unroll
            for (int i = 0; i < NG; ++i) {
                ffma2(acc[i][j], wc[i].x, s.x);
                ffma2(acc[i][j], wc[i].y, s.y);
            }
        }
    }
}

// scalar single-row dot (bridge)
template<int GW, int K4>
__device__ __forceinline__ float dot1(const float* __restrict__ wbase, int g,
                                      const float* __restrict__ srow, float acc)
{
    const float4* w4 = reinterpret_cast<const float4*>(wbase);
    const float4* s4 = reinterpret_cast<const float4*>(srow);
    #pragma unroll 4
    for (int k4 = 0; k4 < K4; ++k4) {
        float4 w = __ldg(&w4[k4 * GW + g]);
        float4 s = s4[k4];
        acc = fmaf(w.x, s.x, acc);
        acc = fmaf(w.y, s.y, acc);
        acc = fmaf(w.z, s.z, acc);
        acc = fmaf(w.w, s.w, acc);
    }
    return acc;
}

#define ZACC(A, NI) { _Pragma("unroll") for (int i = 0; i < NI; ++i) \
                      _Pragma("unroll") for (int j = 0; j < 8; ++j) A[i][j] = 0ull; }

// ---------------------------------------------------------------------------
// Main fused kernel: 128 threads, 8 rows, 4g x 8r tile
// ---------------------------------------------------------------------------
__global__ void __launch_bounds__(NTHREADS, 2)
fused_kernel(const float* __restrict__ x, const int* __restrict__ plen_p,
             const float* __restrict__ fc2w, const float* __restrict__ fc2b,
             float* __restrict__ out)
{
    extern __shared__ float sm[];
    float (*st)[384]  = (float (*)[384])(sm + SM_ST);
    float (*c0s)[128] = (float (*)[128])(sm + SM_C0);
    float (*c1s)[128] = (float (*)[128])(sm + SM_C1);
    float (*gb0)[512] = (float (*)[512])(sm + SM_GB0);
    float (*gb1)[512] = (float (*)[512])(sm + SM_GB1);
    float (*gbH)[64]  = (float (*)[64])(sm + SM_GBH);
    __shared__ float fc2ws[128];
    __shared__ float fc2bs[2];

    const int tid = threadIdx.x;
    const int rbase = blockIdx.x * NROWS;
    const float* S = g_scratch;
    const int plen = plen_p[0];

    // init
    for (int i = tid; i < NROWS * 384; i += NTHREADS) (&st[0][0])[i] = 0.f;
    for (int i = tid; i < NROWS * 128; i += NTHREADS) { (&c0s[0][0])[i] = 0.f; (&c1s[0][0])[i] = 0.f; }
    fc2ws[tid] = fc2w[tid];
    if (tid < 2) fc2bs[tid] = fc2b[tid];
    __syncthreads();
    if (tid < 32) {
        int r = tid >> 2, k = tid & 3;
        st[r][k] = x[(rbase + r) * 256 + k];
    }
    __syncthreads();

    // ---------------- LSTM encoder: layer wavefront ----------------
    // Each thread: gates {tid, tid+128, tid+256, tid+384}, all 8 rows.
    for (int t = 0; t <= SEQ; ++t) {
        {
            unsigned long long acc[4][8];
            if (t < SEQ) {
                ZACC(acc, 4);
                dotG8<4, 512, 33>(S + OFF_W0, tid, &st[0][0], acc);
                #pragma unroll
                for (int i = 0; i < 4; ++i) {
                    float b = S[OFF_B0 + tid + 128 * i];
                    #pragma unroll
                    for (int j = 0; j < 8; ++j)
                        gb0[j][tid + 128 * i] = b + red2(acc[i][j]);
                }
            }
            if (t > 0) {
                ZACC(acc, 4);
                dotG8<4, 512, 64>(S + OFF_W1, tid, &st[0][4], acc);
                #pragma unroll
                for (int i = 0; i < 4; ++i) {
                    float b = S[OFF_B1 + tid + 128 * i];
                    #pragma unroll
                    for (int j = 0; j < 8; ++j)
                        gb1[j][tid + 128 * i] = b + red2(acc[i][j]);
                }
            }
        }
        __syncthreads();

        // updates: h0(t), h1(t-1), stage x(t+1)
        if (t < SEQ) {
            #pragma unroll
            for (int p = 0; p < 8; ++p) {
                int idx = tid + p * NTHREADS;        // [0, 1024)
                int r = idx >> 7, d = idx & 127;
                float gi = sigf(gb0[r][d]);
                float gf = sigf(gb0[r][128 + d]);
                float gg = tanhfast(gb0[r][256 + d]);
                float go = sigf(gb0[r][384 + d]);
                float cn = gf * c0s[r][d] + gi * gg;
                c0s[r][d] = cn;
                st[r][4 + d] = go * tanhfast(cn);
            }
        }
        if (t > 0) {
            #pragma unroll
            for (int p = 0; p < 8; ++p) {
                int idx = tid + p * NTHREADS;
                int r = idx >> 7, d = idx & 127;
                float gi = sigf(gb1[r][d]);
                float gf = sigf(gb1[r][128 + d]);
                float gg = tanhfast(gb1[r][256 + d]);
                float go = sigf(gb1[r][384 + d]);
                float cn = gf * c1s[r][d] + gi * gg;
                c1s[r][d] = cn;
                st[r][132 + d] = go * tanhfast(cn);
            }
        }
        if (t + 1 < SEQ && tid < 32) {
            int r = tid >> 2, k = tid & 3;
            st[r][k] = x[(rbase + r) * 256 + (t + 1) * 4 + k];
        }
        __syncthreads();
    }

    // ---------------- bridge ----------------
    #pragma unroll
    for (int p = 0; p < 16; ++p) {
        int idx = tid + p * NTHREADS;          // [0, 2048)
        int l = idx >> 10;
        int rem = idx & 1023;
        int r = rem >> 7, d = rem & 127;
        float acc = S[OFF_BB + d];
        acc = dot1<128, 32>(S + OFF_BR, d, &st[r][4 + 128 * l], acc);
        gb0[r][l * 128 + d] = tanhfast(acc);
    }
    __syncthreads();
    // restage: inp = h1(final), hd0 = hg0, hd1 = hg1
    {
        float inpv[8], g0v[8], g1v[8];
        #pragma unroll
        for (int p = 0; p < 8; ++p) {
            int idx = tid + p * NTHREADS;      // [0, 1024)
            int r = idx >> 7, d = idx & 127;
            inpv[p] = st[r][132 + d];
            g0v[p] = gb0[r][d];
            g1v[p] = gb0[r][128 + d];
        }
        __syncthreads();
        #pragma unroll
        for (int p = 0; p < 8; ++p) {
            int idx = tid + p * NTHREADS;
            int r = idx >> 7, d = idx & 127;
            st[r][d] = inpv[p];
            st[r][128 + d] = g0v[p];
            st[r][256 + d] = g1v[p];
        }
    }
    __syncthreads();

    // ---------------- GRU decoder + folded head ----------------
    // roles (128 threads, 8 rows each):
    //  tid <64   : rz gates   NG=4 GW=256 (g = tid, +64 stride), K4=64
    //  tid 64..95: n-in+n-hn  NG=4 GW=128 (g = tid-64, +32 stride), K4=32+32
    //  tid 96..127: fc1(td-1) NG=2 GW=64  (g = tid-96, +32 stride), K4=32
    //  tid 96..111: fc2(td-1) in phase G1
    for (int td = 0; td <= plen; ++td) {
        // --- phase G0: layer-0 gates + fc1(td-1) ---
        if (tid < 64) {
            if (td < plen) {
                unsigned long long acc[4][8];
                ZACC(acc, 4);
                dotG8<4, 256, 64>(S + OFF_GRZ0, tid, &st[0][0], acc);
                #pragma unroll
                for (int i = 0; i < 4; ++i) {
                    float b = S[OFF_BRZ0 + tid + 64 * i];
                    #pragma unroll
                    for (int j = 0; j < 8; ++j)
                        gb0[j][tid + 64 * i] = b + red2(acc[i][j]);
                }
            }
        } else if (tid < 96) {
            if (td < plen) {
                int g = tid - 64;
                unsigned long long acc[4][8];
                ZACC(acc, 4);
                dotG8<4, 128, 32>(S + OFF_WIN0, g, &st[0][0], acc);
                #pragma unroll
                for (int i = 0; i < 4; ++i) {
                    float b = S[OFF_BIN0 + g + 32 * i];
                    #pragma unroll
                    for (int j = 0; j < 8; ++j)
                        gb0[j][256 + g + 32 * i] = b + red2(acc[i][j]);
                }
                ZACC(acc, 4);
                dotG8<4, 128, 32>(S + OFF_WHN0, g, &st[0][128], acc);
                #pragma unroll
                for (int i = 0; i < 4; ++i) {
                    float b = S[OFF_BHN0 + g + 32 * i];
                    #pragma unroll
                    for (int j = 0; j < 8; ++j)
                        gb0[j][384 + g + 32 * i] = b + red2(acc[i][j]);
                }
            }
        } else {
            if (td > 0) {
                int g = tid - 96;
                unsigned long long acc[2][8];
                ZACC(acc, 2);
                dotG8<2, 64, 32>(S + OFF_FC1, g, &st[0][256], acc);
                #pragma unroll
                for (int i = 0; i < 2; ++i) {
                    float b = S[OFF_FC1B + g + 32 * i];
                    #pragma unroll
                    for (int j = 0; j < 8; ++j)
                        gbH[j][g + 32 * i] = fmaxf(b + red2(acc[i][j]), 0.f);
                }
            }
        }
        __syncthreads();

        // --- update h0 ---
        if (td < plen) {
            #pragma unroll
            for (int p = 0; p < 8; ++p) {
                int idx = tid + p * NTHREADS;   // [0, 1024)
                int r = idx >> 7, d = idx & 127;
                float rv = sigf(gb0[r][d]);
                float zv = sigf(gb0[r][128 + d]);
                float nv = tanhfast(gb0[r][256 + d] + rv * gb0[r][384 + d]);
                float hold = st[r][128 + d];
                st[r][128 + d] = (1.f - zv) * nv + zv * hold;
            }
        }
        __syncthreads();

        // --- phase G1: layer-1 gates + fc2(td-1) + store ---
        if (tid < 64) {
            if (td < plen) {
                unsigned long long acc[4][8];
                ZACC(acc, 4);
                dotG8<4, 256, 64>(S + OFF_GRZ1, tid, &st[0][128], acc);
                #pragma unroll
                for (int i = 0; i < 4; ++i) {
                    float b = S[OFF_BRZ1 + tid + 64 * i];
                    #pragma unroll
                    for (int j = 0; j < 8; ++j)
                        gb0[j][tid + 64 * i] = b + red2(acc[i][j]);
                }
            }
        } else if (tid < 96) {
            if (td < plen) {
                int g = tid - 64;
                unsigned long long acc[4][8];
                ZACC(acc, 4);
                dotG8<4, 128, 32>(S + OFF_WIN1, g, &st[0][128], acc);
                #pragma unroll
                for (int i = 0; i < 4; ++i) {
                    float b = S[OFF_BIN1 + g + 32 * i];
                    #pragma unroll
                    for (int j = 0; j < 8; ++j)
                        gb0[j][256 + g + 32 * i] = b + red2(acc[i][j]);
                }
                ZACC(acc, 4);
                dotG8<4, 128, 32>(S + OFF_WHN1, g, &st[0][256], acc);
                #pragma unroll
                for (int i = 0; i < 4; ++i) {
                    float b = S[OFF_BHN1 + g + 32 * i];
                    #pragma unroll
                    for (int j = 0; j < 8; ++j)
                        gb0[j][384 + g + 32 * i] = b + red2(acc[i][j]);
                }
            }
        } else if (tid < 112) {
            if (td > 0) {
                int lo = tid - 96;
                int r = lo >> 1, o = lo & 1;
                float a = fc2bs[o];
                #pragma unroll 8
                for (int k = 0; k < 64; ++k) a = fmaf(fc2ws[o * 64 + k], gbH[r][k], a);
                out[((rbase + r) * plen + (td - 1)) * 2 + o] = a;
            }
        }
        __syncthreads();

        // --- update h1, write next inp ---
        if (td < plen) {
            #pragma unroll
            for (int p = 0; p < 8; ++p) {
                int idx = tid + p * NTHREADS;
                int r = idx >> 7, d = idx & 127;
                float rv = sigf(gb0[r][d]);
                float zv = sigf(gb0[r][128 + d]);
                float nv = tanhfast(gb0[r][256 + d] + rv * gb0[r][384 + d]);
                float hold = st[r][256 + d];
                float hnew = (1.f - zv) * nv + zv * hold;
                st[r][256 + d] = hnew;
                st[r][d] = hnew;
            }
        }
        __syncthreads();
    }
}

// ---------------------------------------------------------------------------
// launch
// ---------------------------------------------------------------------------
extern "C" void kernel_launch(void* const* d_in, const int* in_sizes, int n_in,
                              void* d_out, int out_size)
{
    const float* x        = (const float*)d_in[0];
    const int*   pred_len = (const int*)  d_in[1];
    const float* wih0  = (const float*)d_in[2];
    const float* whh0  = (const float*)d_in[3];
    const float* bih0  = (const float*)d_in[4];
    const float* bhh0  = (const float*)d_in[5];
    const float* wih1  = (const float*)d_in[6];
    const float* whh1  = (const float*)d_in[7];
    const float* bih1  = (const float*)d_in[8];
    const float* bhh1  = (const float*)d_in[9];
    const float* gwih0 = (const float*)d_in[10];
    const float* gwhh0 = (const float*)d_in[11];
    const float* gbih0 = (const float*)d_in[12];
    const float* gbhh0 = (const float*)d_in[13];
    const float* gwih1 = (const float*)d_in[14];
    const float* gwhh1 = (const float*)d_in[15];
    const float* gbih1 = (const float*)d_in[16];
    const float* gbhh1 = (const float*)d_in[17];
    const float* brw   = (const float*)d_in[18];
    const float* brb   = (const float*)d_in[19];
    const float* fc1w  = (const float*)d_in[20];
    const float* fc1b  = (const float*)d_in[21];
    const float* fc2w  = (const float*)d_in[22];
    const float* fc2b  = (const float*)d_in[23];
    float* out = (float*)d_out;

    static bool attr_set = false;
    if (!attr_set) {
        cudaFuncSetAttribute(fused_kernel,
                             cudaFuncAttributeMaxDynamicSharedMemorySize, SMEM_BYTES);
        attr_set = true;
    }

    int prep_blocks = (SCRATCH_TOTAL + 255) / 256;
    prep_kernel<<<prep_blocks, 256>>>(wih0, whh0, bih0, bhh0,
                                      wih1, whh1, bih1, bhh1,
                                      gwih0, gwhh0, gbih0, gbhh0,
                                      gwih1, gwhh1, gbih1, gbhh1,
                                      brw, brb, fc1w, fc1b);
    fused_kernel<<<NBLOCKS, NTHREADS, SMEM_BYTES>>>(x, pred_len, fc2w, fc2b, out);
}